// round 4
// baseline (speedup 1.0000x reference)
#include <cuda_runtime.h>
#include <cuda_bf16.h>
#include <cstdint>
#include <math.h>

// Problem constants (fixed by reference setup)
#define TQS 2048
#define TKS 2048
#define DDIM 2048
#define IDIM 2048
#define NHEAD 16
#define HDIM 128
#define NBATCH 2
#define NBH (NBATCH*NHEAD)

typedef __nv_bfloat16 bf16;

// ---------------- scratch (device globals; no runtime allocation) -----------
// Total ~144 MB (was 912 MB with materialized scores/probs).
__device__ bf16  g_Xq [(size_t)NBATCH*TQS*DDIM];
__device__ bf16  g_Xkv[(size_t)NBATCH*TKS*DDIM];
__device__ bf16  g_Wq [(size_t)IDIM*DDIM];
__device__ bf16  g_Wk [(size_t)IDIM*DDIM];
__device__ bf16  g_Wv [(size_t)IDIM*DDIM];
__device__ bf16  g_Wo [(size_t)DDIM*IDIM];
__device__ bf16  g_Q  [(size_t)NBATCH*TQS*IDIM];
__device__ bf16  g_K  [(size_t)NBATCH*TKS*IDIM];
__device__ bf16  g_V  [(size_t)NBATCH*TKS*IDIM];
__device__ bf16  g_Vt [(size_t)NBATCH*IDIM*TKS];     // per-batch transpose [b][i][tk]
__device__ bf16  g_Ctx[(size_t)NBATCH*TQS*IDIM];
__device__ int   g_maskByte;

// ---------------- GEMM core: C(128x128) += A(128xK) * B(128xK)^T ------------
#define BM 128
#define BN 128
#define BK 32
#define SAST 40   // padded smem stride (bf16 elems) for dense GEMM core
#define FST 136   // padded smem stride for flash tiles

__device__ __forceinline__ void mma16816(float c[4], const uint32_t a[4], const uint32_t b[2]) {
    asm volatile(
        "mma.sync.aligned.m16n8k16.row.col.f32.bf16.bf16.f32 "
        "{%0,%1,%2,%3}, {%4,%5,%6,%7}, {%8,%9}, {%0,%1,%2,%3};\n"
        : "+f"(c[0]), "+f"(c[1]), "+f"(c[2]), "+f"(c[3])
        : "r"(a[0]), "r"(a[1]), "r"(a[2]), "r"(a[3]), "r"(b[0]), "r"(b[1]));
}

// NT GEMM: acc[mi][ni][4] over warp tile; 256 threads, 8 warps (2m x 4n)
__device__ __forceinline__ void gemm_core(
    const bf16* __restrict__ A, int lda,
    const bf16* __restrict__ Bm, int ldb,
    int kBegin, int kEnd, float (&acc)[4][4][4])
{
    __shared__ bf16 SA[128 * SAST];
    __shared__ bf16 SB[128 * SAST];

    const int t    = threadIdx.x;
    const int lane = t & 31;
    const int warp = t >> 5;
    const int wm   = warp & 1;      // 0..1
    const int wn   = warp >> 1;     // 0..3
    const int grp  = lane >> 2;     // 0..7
    const int tid4 = lane & 3;      // 0..3

    for (int k0 = kBegin; k0 < kEnd; k0 += BK) {
#pragma unroll
        for (int i = 0; i < 2; i++) {
            int idx = t + i * 256;
            int r = idx >> 2;
            int c = (idx & 3) << 3;
            *(float4*)(SA + r * SAST + c) = *(const float4*)(A  + (size_t)r * lda + k0 + c);
            *(float4*)(SB + r * SAST + c) = *(const float4*)(Bm + (size_t)r * ldb + k0 + c);
        }
        __syncthreads();
#pragma unroll
        for (int kk = 0; kk < BK; kk += 16) {
            uint32_t af[4][4];
            uint32_t bfr[4][2];
#pragma unroll
            for (int mi = 0; mi < 4; mi++) {
                int r0 = wm * 64 + mi * 16 + grp;
                const bf16* p = SA + r0 * SAST + kk + tid4 * 2;
                af[mi][0] = *(const uint32_t*)p;
                af[mi][1] = *(const uint32_t*)(p + 8 * SAST);
                af[mi][2] = *(const uint32_t*)(p + 8);
                af[mi][3] = *(const uint32_t*)(p + 8 * SAST + 8);
            }
#pragma unroll
            for (int ni = 0; ni < 4; ni++) {
                int c0 = wn * 32 + ni * 8 + grp;
                const bf16* p = SB + c0 * SAST + kk + tid4 * 2;
                bfr[ni][0] = *(const uint32_t*)p;
                bfr[ni][1] = *(const uint32_t*)(p + 8);
            }
#pragma unroll
            for (int mi = 0; mi < 4; mi++)
#pragma unroll
                for (int ni = 0; ni < 4; ni++)
                    mma16816(acc[mi][ni], af[mi], bfr[ni]);
        }
        __syncthreads();
    }
}

#define GEMM_PROLOG()                              \
    float acc[4][4][4];                            \
    _Pragma("unroll") for (int a_=0;a_<4;a_++)     \
    _Pragma("unroll") for (int b_=0;b_<4;b_++)     \
    _Pragma("unroll") for (int c_=0;c_<4;c_++) acc[a_][b_][c_] = 0.f;

#define EPI_VARS()                                  \
    const int lane = threadIdx.x & 31;              \
    const int warp = threadIdx.x >> 5;              \
    const int wm = warp & 1, wn = warp >> 1;        \
    const int grp = lane >> 2, tid4 = lane & 3;

// ---------------- mode kernels ----------------------------------------------

// Q/K/V projection: C = X * W^T + bias -> bf16
__global__ __launch_bounds__(256) void k_proj(
    const bf16* __restrict__ X, const bf16* __restrict__ W,
    const float* __restrict__ bias, bf16* __restrict__ Cout)
{
    const int m0 = blockIdx.y * BM;
    const int n0 = blockIdx.x * BN;
    GEMM_PROLOG();
    gemm_core(X + (size_t)m0 * DDIM, DDIM, W + (size_t)n0 * DDIM, DDIM, 0, DDIM, acc);
    EPI_VARS();
#pragma unroll
    for (int mi = 0; mi < 4; mi++)
#pragma unroll
        for (int ni = 0; ni < 4; ni++)
#pragma unroll
            for (int hh = 0; hh < 2; hh++) {
                int r = m0 + wm * 64 + mi * 16 + grp + hh * 8;
                int c = n0 + wn * 32 + ni * 8 + tid4 * 2;
                float v0 = acc[mi][ni][hh * 2 + 0] + bias[c];
                float v1 = acc[mi][ni][hh * 2 + 1] + bias[c + 1];
                __nv_bfloat162 o;
                o.x = __float2bfloat16(v0);
                o.y = __float2bfloat16(v1);
                *(__nv_bfloat162*)&Cout[(size_t)r * IDIM + c] = o;
            }
}

// ---------------- fused flash attention -------------------------------------
// One CTA per (q-tile of 128, b*h). 8 warps, each owns 16 q-rows.
// Q fragments persist in registers; K/V tiles staged through dynamic smem.
// Online softmax; P reused directly as mma A-fragments (no smem round trip).
__global__ __launch_bounds__(256) void k_flash(const unsigned char* __restrict__ maskRaw)
{
    const int qt = blockIdx.x, bh = blockIdx.y;
    const int b = bh >> 4, h = bh & 15;

    extern __shared__ bf16 sm[];
    bf16* SK = sm;                 // [128][FST]
    bf16* SV = sm + 128 * FST;     // [128][FST]
    __shared__ unsigned char mk[128];

    const int t = threadIdx.x, lane = t & 31, w = t >> 5;
    const int grp = lane >> 2, tid4 = lane & 3;

    // --- stage Q tile through SK, extract persistent A-fragments ---
    const bf16* Qg = g_Q + ((size_t)(b * TQS + qt * 128)) * IDIM + h * HDIM;
#pragma unroll
    for (int i = 0; i < 8; i++) {
        int idx = t + i * 256;
        int r = idx >> 4;
        int c = (idx & 15) * 8;
        *(float4*)(SK + r * FST + c) = *(const float4*)(Qg + (size_t)r * IDIM + c);
    }
    __syncthreads();
    uint32_t qf[8][4];
    {
        const int r0 = w * 16 + grp;
#pragma unroll
        for (int kc = 0; kc < 8; kc++) {
            const bf16* p = SK + r0 * FST + kc * 16 + tid4 * 2;
            qf[kc][0] = *(const uint32_t*)p;
            qf[kc][1] = *(const uint32_t*)(p + 8 * FST);
            qf[kc][2] = *(const uint32_t*)(p + 8);
            qf[kc][3] = *(const uint32_t*)(p + 8 * FST + 8);
        }
    }
    __syncthreads();

    float m0 = -INFINITY, m1 = -INFINITY, l0 = 0.f, l1 = 0.f;
    float ao[16][4];
#pragma unroll
    for (int ni = 0; ni < 16; ni++)
#pragma unroll
        for (int j = 0; j < 4; j++) ao[ni][j] = 0.f;

    const int useByte = g_maskByte;
    const float scale = 0.088388347648318447f;  // 1/sqrt(128)
    const int q0 = qt * 128 + w * 16 + grp;     // rows for c0/c1
    const int q1 = q0 + 8;                      // rows for c2/c3

    const bf16* Vtb = g_Vt + (size_t)b * IDIM * TKS + (size_t)(h * HDIM) * TKS;

    for (int kt = 0; kt <= qt; kt++) {
        // --- load K tile [key][d] and V tile [d][key] ---
        const bf16* Kg = g_K + ((size_t)(b * TKS + kt * 128)) * IDIM + h * HDIM;
        const bf16* Vg = Vtb + kt * 128;
#pragma unroll
        for (int i = 0; i < 8; i++) {
            int idx = t + i * 256;
            int r = idx >> 4;
            int c = (idx & 15) * 8;
            *(float4*)(SK + r * FST + c) = *(const float4*)(Kg + (size_t)r * IDIM + c);
            *(float4*)(SV + r * FST + c) = *(const float4*)(Vg + (size_t)r * TKS + c);
        }
        if (t < 128) {
            int k = kt * 128 + t;
            int mv = useByte ? (int)maskRaw[(size_t)b * TKS + k]
                             : ((const int*)maskRaw)[(size_t)b * TKS + k];
            mk[t] = (unsigned char)(mv != 0);
        }
        __syncthreads();

        // --- S = Q K^T (16x128 per warp) ---
        float as_[16][4];
#pragma unroll
        for (int ni = 0; ni < 16; ni++)
#pragma unroll
            for (int j = 0; j < 4; j++) as_[ni][j] = 0.f;
#pragma unroll
        for (int kc = 0; kc < 8; kc++) {
#pragma unroll
            for (int ni = 0; ni < 16; ni++) {
                const bf16* p = SK + (ni * 8 + grp) * FST + kc * 16 + tid4 * 2;
                uint32_t bb[2];
                bb[0] = *(const uint32_t*)p;
                bb[1] = *(const uint32_t*)(p + 8);
                mma16816(as_[ni], qf[kc], bb);
            }
        }

        // --- scale + causal + padding mask; row max ---
        float tm0 = -INFINITY, tm1 = -INFINITY;
#pragma unroll
        for (int ni = 0; ni < 16; ni++) {
            int kc0 = ni * 8 + tid4 * 2;
            int kg = kt * 128 + kc0;
            bool pm0 = mk[kc0] != 0, pm1 = mk[kc0 + 1] != 0;
            float s0 = (kg     > q0 || pm0) ? -INFINITY : as_[ni][0] * scale;
            float s1 = (kg + 1 > q0 || pm1) ? -INFINITY : as_[ni][1] * scale;
            float s2 = (kg     > q1 || pm0) ? -INFINITY : as_[ni][2] * scale;
            float s3 = (kg + 1 > q1 || pm1) ? -INFINITY : as_[ni][3] * scale;
            as_[ni][0] = s0; as_[ni][1] = s1; as_[ni][2] = s2; as_[ni][3] = s3;
            tm0 = fmaxf(tm0, fmaxf(s0, s1));
            tm1 = fmaxf(tm1, fmaxf(s2, s3));
        }
        tm0 = fmaxf(tm0, __shfl_xor_sync(0xffffffffu, tm0, 1));
        tm0 = fmaxf(tm0, __shfl_xor_sync(0xffffffffu, tm0, 2));
        tm1 = fmaxf(tm1, __shfl_xor_sync(0xffffffffu, tm1, 1));
        tm1 = fmaxf(tm1, __shfl_xor_sync(0xffffffffu, tm1, 2));

        // --- online softmax update ---
        float mn0 = fmaxf(m0, tm0), mn1 = fmaxf(m1, tm1);
        float f0 = __expf(m0 - mn0), f1 = __expf(m1 - mn1);
        m0 = mn0; m1 = mn1;

        float rs0 = 0.f, rs1 = 0.f;
#pragma unroll
        for (int ni = 0; ni < 16; ni++) {
            float p0 = __expf(as_[ni][0] - mn0);
            float p1 = __expf(as_[ni][1] - mn0);
            float p2 = __expf(as_[ni][2] - mn1);
            float p3 = __expf(as_[ni][3] - mn1);
            as_[ni][0] = p0; as_[ni][1] = p1; as_[ni][2] = p2; as_[ni][3] = p3;
            rs0 += p0 + p1;
            rs1 += p2 + p3;
        }
        rs0 += __shfl_xor_sync(0xffffffffu, rs0, 1);
        rs0 += __shfl_xor_sync(0xffffffffu, rs0, 2);
        rs1 += __shfl_xor_sync(0xffffffffu, rs1, 1);
        rs1 += __shfl_xor_sync(0xffffffffu, rs1, 2);
        l0 = l0 * f0 + rs0;
        l1 = l1 * f1 + rs1;

        // --- rescale O accumulator ---
#pragma unroll
        for (int ni = 0; ni < 16; ni++) {
            ao[ni][0] *= f0; ao[ni][1] *= f0;
            ao[ni][2] *= f1; ao[ni][3] *= f1;
        }

        // --- O += P V : P (fp32 acc layout) == A-fragment layout identity ---
#pragma unroll
        for (int kc = 0; kc < 8; kc++) {
            uint32_t pf[4];
            __nv_bfloat162 h0 = __float22bfloat162_rn(make_float2(as_[2*kc][0],   as_[2*kc][1]));
            __nv_bfloat162 h1 = __float22bfloat162_rn(make_float2(as_[2*kc][2],   as_[2*kc][3]));
            __nv_bfloat162 h2 = __float22bfloat162_rn(make_float2(as_[2*kc+1][0], as_[2*kc+1][1]));
            __nv_bfloat162 h3 = __float22bfloat162_rn(make_float2(as_[2*kc+1][2], as_[2*kc+1][3]));
            pf[0] = *(uint32_t*)&h0;
            pf[1] = *(uint32_t*)&h1;
            pf[2] = *(uint32_t*)&h2;
            pf[3] = *(uint32_t*)&h3;
#pragma unroll
            for (int ni = 0; ni < 16; ni++) {
                const bf16* p = SV + (ni * 8 + grp) * FST + kc * 16 + tid4 * 2;
                uint32_t bb[2];
                bb[0] = *(const uint32_t*)p;
                bb[1] = *(const uint32_t*)(p + 8);
                mma16816(ao[ni], pf, bb);
            }
        }
        __syncthreads();
    }

    // --- normalize and write ctx (bf16) ---
    const float inv0 = 1.f / l0, inv1 = 1.f / l1;
    bf16* Cg = g_Ctx + ((size_t)(b * TQS + qt * 128 + w * 16)) * IDIM + h * HDIM;
#pragma unroll
    for (int ni = 0; ni < 16; ni++) {
        int c = ni * 8 + tid4 * 2;
        __nv_bfloat162 o0 = __float22bfloat162_rn(make_float2(ao[ni][0] * inv0, ao[ni][1] * inv0));
        __nv_bfloat162 o1 = __float22bfloat162_rn(make_float2(ao[ni][2] * inv1, ao[ni][3] * inv1));
        *(__nv_bfloat162*)(Cg + (size_t)grp * IDIM + c)       = o0;
        *(__nv_bfloat162*)(Cg + (size_t)(grp + 8) * IDIM + c) = o1;
    }
}

// out = query + (ctx * Wo^T + bo) * sigmoid(gate)
__global__ __launch_bounds__(256) void k_out(
    const float* __restrict__ query, const float* __restrict__ bo,
    const float* __restrict__ gate, float* __restrict__ out)
{
    const int m0 = blockIdx.y * BM;
    const int n0 = blockIdx.x * BN;
    GEMM_PROLOG();
    gemm_core(g_Ctx + (size_t)m0 * IDIM, IDIM, g_Wo + (size_t)n0 * IDIM, IDIM, 0, IDIM, acc);
    EPI_VARS();
#pragma unroll
    for (int mi = 0; mi < 4; mi++)
#pragma unroll
        for (int ni = 0; ni < 4; ni++)
#pragma unroll
            for (int hh = 0; hh < 2; hh++) {
                int r = m0 + wm * 64 + mi * 16 + grp + hh * 8;
                int c = n0 + wn * 32 + ni * 8 + tid4 * 2;
                float g0 = 1.f / (1.f + expf(-gate[c]));
                float g1 = 1.f / (1.f + expf(-gate[c + 1]));
                float v0 = (acc[mi][ni][hh * 2 + 0] + bo[c])     * g0;
                float v1 = (acc[mi][ni][hh * 2 + 1] + bo[c + 1]) * g1;
                float2 qv = *(const float2*)&query[(size_t)r * DDIM + c];
                float2 o; o.x = qv.x + v0; o.y = qv.y + v1;
                *(float2*)&out[(size_t)r * DDIM + c] = o;
            }
}

// V transpose per batch: Vt[b][i][tk] = V[b*TK + tk][i]
__global__ void k_transpose()
{
    __shared__ bf16 tile[32][33];
    const int b = blockIdx.z;
    const int i0 = blockIdx.x * 32;
    const int t0 = blockIdx.y * 32;
    const int x = threadIdx.x, y = threadIdx.y;   // (32, 8)
#pragma unroll
    for (int j = 0; j < 32; j += 8)
        tile[y + j][x] = g_V[(size_t)(b * TKS + t0 + y + j) * IDIM + i0 + x];
    __syncthreads();
#pragma unroll
    for (int j = 0; j < 32; j += 8)
        g_Vt[(size_t)b * IDIM * TKS + (size_t)(i0 + y + j) * TKS + t0 + x] = tile[x][y + j];
}

// fp32 -> bf16 conversion (n multiple of 4)
__global__ void k_cvt(const float* __restrict__ src, bf16* __restrict__ dst, int n)
{
    int i = (blockIdx.x * blockDim.x + threadIdx.x) * 4;
    if (i < n) {
        float4 v = *(const float4*)(src + i);
        __nv_bfloat162 a, b;
        a.x = __float2bfloat16(v.x); a.y = __float2bfloat16(v.y);
        b.x = __float2bfloat16(v.z); b.y = __float2bfloat16(v.w);
        *(__nv_bfloat162*)(dst + i)     = a;
        *(__nv_bfloat162*)(dst + i + 2) = b;
    }
}

// detect mask storage layout: byte 4095 == 1 => 1-byte bool; == 0 => int32
__global__ void k_detect(const unsigned char* __restrict__ mask)
{
    g_maskByte = (mask[(size_t)NBATCH * TKS - 1] != 0) ? 1 : 0;
}

// ---------------- launch -----------------------------------------------------
extern "C" void kernel_launch(void* const* d_in, const int* in_sizes, int n_in,
                              void* d_out, int out_size)
{
    const float* query = (const float*)d_in[0];
    const float* kv    = (const float*)d_in[1];
    const unsigned char* mask = (const unsigned char*)d_in[2];
    const float* Wq = (const float*)d_in[3];
    const float* bq = (const float*)d_in[4];
    const float* Wk = (const float*)d_in[5];
    const float* bk = (const float*)d_in[6];
    const float* Wv = (const float*)d_in[7];
    const float* bv = (const float*)d_in[8];
    const float* Wo = (const float*)d_in[9];
    const float* bo = (const float*)d_in[10];
    const float* gate = (const float*)d_in[11];
    float* out = (float*)d_out;

    // symbol addresses
    bf16 *pXq, *pXkv, *pWq, *pWk, *pWv, *pWo, *pQ, *pK, *pV;
    cudaGetSymbolAddress((void**)&pXq,  g_Xq);
    cudaGetSymbolAddress((void**)&pXkv, g_Xkv);
    cudaGetSymbolAddress((void**)&pWq,  g_Wq);
    cudaGetSymbolAddress((void**)&pWk,  g_Wk);
    cudaGetSymbolAddress((void**)&pWv,  g_Wv);
    cudaGetSymbolAddress((void**)&pWo,  g_Wo);
    cudaGetSymbolAddress((void**)&pQ,   g_Q);
    cudaGetSymbolAddress((void**)&pK,   g_K);
    cudaGetSymbolAddress((void**)&pV,   g_V);

    // allow 68KB dynamic smem for the flash kernel (idempotent)
    static int attrSet = 0;
    const int FLASH_SMEM = 2 * 128 * FST * (int)sizeof(bf16);  // 69632
    if (!attrSet) {
        cudaFuncSetAttribute(k_flash, cudaFuncAttributeMaxDynamicSharedMemorySize, FLASH_SMEM);
        attrSet = 1;
    }

    k_detect<<<1, 1>>>(mask);

    const int nTok = NBATCH * TQS * DDIM;   // 8388608
    const int nW   = IDIM * DDIM;           // 4194304
    k_cvt<<<nTok / 1024, 256>>>(query, pXq,  nTok);
    k_cvt<<<nTok / 1024, 256>>>(kv,    pXkv, nTok);
    k_cvt<<<nW   / 1024, 256>>>(Wq,    pWq,  nW);
    k_cvt<<<nW   / 1024, 256>>>(Wk,    pWk,  nW);
    k_cvt<<<nW   / 1024, 256>>>(Wv,    pWv,  nW);
    k_cvt<<<nW   / 1024, 256>>>(Wo,    pWo,  nW);

    dim3 gProj(IDIM / BN, NBATCH * TQS / BM);        // (16, 32)
    k_proj<<<gProj, 256>>>(pXq,  pWq, bq, pQ);
    k_proj<<<gProj, 256>>>(pXkv, pWk, bk, pK);
    k_proj<<<gProj, 256>>>(pXkv, pWv, bv, pV);

    k_transpose<<<dim3(IDIM / 32, TKS / 32, NBATCH), dim3(32, 8)>>>();

    k_flash<<<dim3(TQS / 128, NBH), 256, FLASH_SMEM>>>(mask);

    k_out<<<dim3(DDIM / BN, NBATCH * TQS / BM), 256>>>(query, bo, gate, out);
}